// round 13
// baseline (speedup 1.0000x reference)
#include <cuda_runtime.h>
#include <math.h>

#define Bn   16
#define Cn   256
#define Hn   48
#define Wn   48
#define HWn  2304
#define NG   40
#define KK   49

typedef unsigned long long ull;

// f32x2 packed-math macros (sm_103a FFMA2 path)
#define FMA2(d,a,b,c) asm("fma.rn.f32x2 %0, %1, %2, %3;" : "=l"(d) : "l"(a), "l"(b), "l"(c))
#define MUL2(d,a,b)   asm("mul.rn.f32x2 %0, %1, %2;"     : "=l"(d) : "l"(a), "l"(b))
#define ADD2(d,a,b)   asm("add.rn.f32x2 %0, %1, %2;"     : "=l"(d) : "l"(a), "l"(b))
#define PK2(d,lo,hi)  asm("mov.b64 %0, {%1, %2};"        : "=l"(d) : "f"(lo), "f"(hi))
#define UPK2(lo,hi,s) asm("mov.b64 {%0, %1}, %2;"        : "=f"(lo), "=f"(hi) : "l"(s))

// Scratch (device globals, zero-initialized at load; padding never written)
__device__ float g_z[Bn * Cn];                                  // GAP [B,C]
__device__ __align__(16) float g_fs[Bn * HWn];                  // channel sum
__device__ float g_basis[NG * KK];                              // bases
__device__ __align__(16) float g_coeffT[3 * Bn * Cn * 16];      // [br,b,c,16n] padded
__device__ float g_G[3 * Bn * 256];                             // Gram/C, n*16+m padded
__device__ float g_s1[3 * Bn * 16];                             // colmean/C padded
__device__ __align__(16) float g_UP[(size_t)Bn * 3 * 16 * HWn]; // [b,br,16n,HW] padded

// ---------------------------------------------------------------------------
// k_prep: block 0 computes the 40 basis kernels; blocks 1..144 zero g_fs
__global__ void k_prep(const float* __restrict__ rw1, const float* __restrict__ rb1,
                       const float* __restrict__ rw2, const float* __restrict__ rb2) {
    int tid = threadIdx.x;
    if (blockIdx.x > 0) {
        int i = (blockIdx.x - 1) * 256 + tid;   // 144*256 = Bn*HWn
        g_fs[i] = 0.f;
        return;
    }
    __shared__ float r[KK], th[KK];
    if (tid < KK) {
        int i = tid / 7, j = tid % 7;
        float gy = (float)i - 3.f, gx = (float)j - 3.f;
        r[tid] = sqrtf(gx * gx + gy * gy + 1e-8f);
        th[tid] = atan2f(gy, gx);
    }
    __syncthreads();

    if (tid < 24) {
        bool inv = tid < 8;
        int i = inv ? tid : (tid - 8);
        int combo = i % 9;
        int d = combo / 3, si = combo % 3;
        float sig = inv ? (4.f + 2.f * (float)si) : (1.f + (float)si);
        float psi[KK];
        float ss = 0.f;
        for (int c = 0; c < KK; ++c) {
            float u = r[c] / sig;
            float g = expf(-0.5f * u * u);
            float p = (d == 0) ? 1.f : ((d == 1) ? u : (u * u - 1.f));
            psi[c] = p * g;
            ss += psi[c] * psi[c];
        }
        float inorm = 1.f / sqrtf(ss + 1e-8f);
        int gi = inv ? tid : (8 + i);
        for (int c = 0; c < KK; ++c) g_basis[gi * KK + c] = psi[c] * inorm;
    }

    if (tid < KK) {
        float rad0 = rb2[0], rad1 = rb2[1];
        for (int h = 0; h < 32; ++h) {
            float t = tanhf(r[tid] * rw1[h] + rb1[h]);
            rad0 += t * rw2[h * 2 + 0];
            rad1 += t * rw2[h * 2 + 1];
        }
        for (int l = 0; l < 8; ++l) {
            float o = (float)(l / 2 + 1);
            float a = (l & 1) ? sinf(o * th[tid]) : cosf(o * th[tid]);
            g_basis[(24 + l) * KK + tid]     = rad0 * a;
            g_basis[(24 + 8 + l) * KK + tid] = rad1 * a;
        }
    }
}

// ---------------------------------------------------------------------------
// k_reduce: float4 loads, same algorithm/atomics as champion.
// grid (16, B), block 288.
__global__ void k_reduce(const float* __restrict__ feat) {
    int b = blockIdx.y, chunk = blockIdx.x, tid = threadIdx.x;
    int lane = tid & 31, w = tid >> 5;           // 9 warps
    __shared__ float zs[16][9];

    float4 f0 = make_float4(0.f, 0.f, 0.f, 0.f);
    float4 f1 = make_float4(0.f, 0.f, 0.f, 0.f);
    const float4* fb = (const float4*)(feat + ((size_t)b * Cn + chunk * 16) * HWn);
    for (int c = 0; c < 16; ++c) {
        const float4* fp = fb + (size_t)c * (HWn / 4);
        float4 a = fp[tid];
        float4 d = fp[tid + 288];
        f0.x += a.x; f0.y += a.y; f0.z += a.z; f0.w += a.w;
        f1.x += d.x; f1.y += d.y; f1.z += d.z; f1.w += d.w;
        float cs = a.x + a.y + a.z + a.w + d.x + d.y + d.z + d.w;
#pragma unroll
        for (int o = 16; o; o >>= 1) cs += __shfl_xor_sync(0xffffffffu, cs, o);
        if (lane == 0) zs[c][w] = cs;
    }
    __syncthreads();
    if (tid < 16) {
        float s = 0.f;
#pragma unroll
        for (int i = 0; i < 9; ++i) s += zs[tid][i];
        g_z[b * Cn + chunk * 16 + tid] = s * (1.f / (float)HWn);
    }
    float* fsb = g_fs + b * HWn;
    atomicAdd(&fsb[4 * tid + 0], f0.x);
    atomicAdd(&fsb[4 * tid + 1], f0.y);
    atomicAdd(&fsb[4 * tid + 2], f0.z);
    atomicAdd(&fsb[4 * tid + 3], f0.w);
    atomicAdd(&fsb[1152 + 4 * tid + 0], f1.x);
    atomicAdd(&fsb[1152 + 4 * tid + 1], f1.y);
    atomicAdd(&fsb[1152 + 4 * tid + 2], f1.z);
    atomicAdd(&fsb[1152 + 4 * tid + 3], f1.w);
}

// ---------------------------------------------------------------------------
// k_mix: blockIdx-split fused kernel. Blocks 0..47 run the MLP (br,b);
// blocks 48..687 run uconv (g,b). Block 288 threads. Shared smem buffer.
#define SBUF_FLOATS 4672

template <int N>
__device__ __forceinline__ void mlp_body(
    int br, int b, int tid,
    const float* __restrict__ w1, const float* __restrict__ b1,
    const float* __restrict__ w2, const float* __restrict__ b2,
    float* sbuf) {
    float* zz = sbuf;            // 256
    float* hp = sbuf + 256;      // 4*64
    float* hh = sbuf + 512;      // 64
    float* sc = sbuf + 576;      // 16*256
    const int NC = N * Cn;
    if (tid < Cn) zz[tid] = g_z[b * Cn + tid];
    __syncthreads();
    if (tid < 256) {
        int j = tid & 63, s = tid >> 6;
        float a = 0.f;
        const float* wp = w1 + (size_t)(64 * s) * 64 + j;
#pragma unroll 8
        for (int c = 0; c < 64; ++c) a += zz[64 * s + c] * wp[c * 64];
        hp[s * 64 + j] = a;
    }
    __syncthreads();
    if (tid < 64)
        hh[tid] = fmaxf(hp[tid] + hp[64 + tid] + hp[128 + tid] + hp[192 + tid] + b1[tid], 0.f);
    __syncthreads();
    if (tid < Cn) {
        int c = tid;
        float acc[N];
#pragma unroll
        for (int n = 0; n < N; ++n) acc[n] = b2[n * Cn + c];
        for (int h2 = 0; h2 < 64; ++h2) {
            float hv = hh[h2];
            const float* wp = w2 + (size_t)h2 * NC + c;
#pragma unroll
            for (int n = 0; n < N; ++n) acc[n] += hv * wp[n * Cn];
        }
#pragma unroll
        for (int n = 0; n < N; ++n) sc[n * Cn + c] = acc[n];
        // transposed, padded coeff store: [c][16] (pad stays zero)
        float4* dst = (float4*)(g_coeffT + ((size_t)(br * Bn + b) * Cn + c) * 16);
#pragma unroll
        for (int k = 0; k < N / 4; ++k)
            dst[k] = make_float4(acc[4 * k], acc[4 * k + 1], acc[4 * k + 2], acc[4 * k + 3]);
    }
    __syncthreads();
    if (tid < N * N) {
        int n = tid / N, m = tid % N;
        float a = 0.f;
#pragma unroll 4
        for (int c = 0; c < Cn; ++c) a += sc[n * Cn + c] * sc[m * Cn + c];
        g_G[(br * Bn + b) * 256 + n * 16 + m] = a * (1.f / (float)Cn);  // n*16+m padded
    } else if (tid < N * N + N) {
        int n = tid - N * N;
        float a = 0.f;
#pragma unroll 4
        for (int c = 0; c < Cn; ++c) a += sc[n * Cn + c];
        g_s1[(br * Bn + b) * 16 + n] = a * (1.f / (float)Cn);
    }
}

__global__ void __launch_bounds__(288)
k_mix(const float* __restrict__ w1i, const float* __restrict__ b1i,
      const float* __restrict__ w2i, const float* __restrict__ b2i,
      const float* __restrict__ w1e, const float* __restrict__ b1e,
      const float* __restrict__ w2e, const float* __restrict__ b2e,
      const float* __restrict__ w1c, const float* __restrict__ b1c,
      const float* __restrict__ w2c, const float* __restrict__ b2c) {
    __shared__ float sbuf[SBUF_FLOATS];
    int bx = blockIdx.x, tid = threadIdx.x;

    if (bx < 48) {
        int br = bx / 16, b = bx % 16;
        if (br == 0)      mlp_body<8>(0, b, tid, w1i, b1i, w2i, b2i, sbuf);
        else if (br == 1) mlp_body<16>(1, b, tid, w1e, b1e, w2e, b2e, sbuf);
        else              mlp_body<16>(2, b, tid, w1c, b1c, w2c, b2c, sbuf);
        return;
    }

    // ---- uconv role ----
    int gb = bx - 48;
    int g = gb % NG, b = gb / NG;
    int br = (g < 8) ? 0 : ((g < 24) ? 1 : 2);
    int nl = g - ((br == 0) ? 0 : ((br == 1) ? 8 : 24));
    float* fp = sbuf;            // 54*54 = 2916
    float* bs = sbuf + 2916;     // 49
    if (tid < KK) bs[tid] = g_basis[g * KK + tid];
    for (int i = tid; i < 54 * 54; i += 288) {
        int row = i / 54, col = i % 54;
        int y = row - 3, x = col - 3;
        fp[i] = (y >= 0 && y < Hn && x >= 0 && x < Wn) ? g_fs[b * HWn + y * Wn + x] : 0.f;
    }
    __syncthreads();

    int x = tid % 48, yg0 = tid / 48;   // yg0 in 0..5
    float* up = g_UP + (((size_t)b * 3 + br) * 16 + nl) * HWn;
#pragma unroll
    for (int it = 0; it < 2; ++it) {
        int y0 = (yg0 + 6 * it) * 4;    // 4 vertically adjacent outputs
        float a0 = 0.f, a1 = 0.f, a2 = 0.f, a3 = 0.f;
#pragma unroll
        for (int ri = 0; ri < 10; ++ri) {
            float t[7];
#pragma unroll
            for (int dx = 0; dx < 7; ++dx) t[dx] = fp[(y0 + ri) * 54 + x + dx];
#pragma unroll
            for (int o = 0; o < 4; ++o) {
                int dy = ri - o;
                if (dy >= 0 && dy < 7) {
                    float s = 0.f;
#pragma unroll
                    for (int dx = 0; dx < 7; ++dx) s += t[dx] * bs[dy * 7 + dx];
                    if (o == 0) a0 += s; else if (o == 1) a1 += s;
                    else if (o == 2) a2 += s; else a3 += s;
                }
            }
        }
        up[(y0 + 0) * Wn + x] = a0;
        up[(y0 + 1) * Wn + x] = a1;
        up[(y0 + 2) * Wn + x] = a2;
        up[(y0 + 3) * Wn + x] = a3;
    }
}

// ---------------------------------------------------------------------------
// k_main v3: channel-split. grid (6, B, 6): z = br*2 + half (128 ch each).
// 576 blocks (~4/SM), block 192, 2 px/thread, 4 independent FFMA2 chains.
__global__ void __launch_bounds__(192)
k_main(const float* __restrict__ lig, const float* __restrict__ lib,
       const float* __restrict__ leg, const float* __restrict__ leb,
       const float* __restrict__ lcg, const float* __restrict__ lcb,
       float* __restrict__ out) {
    int chunk = blockIdx.x, b = blockIdx.y;
    int br = blockIdx.z >> 1, half = blockIdx.z & 1;
    int c0 = half << 7;                  // 0 or 128
    int tid = threadIdx.x;

    const float* lng = (br == 0) ? lig : ((br == 1) ? leg : lcg);
    const float* lnb = (br == 0) ? lib : ((br == 1) ? leb : lcb);

    __shared__ ull s_cf[128 * 16];       // dup-packed coeffs [c][n]  (16 KB)
    __shared__ ulonglong2 s_gb[128];     // (gamma2, beta2)           (2 KB)
    __shared__ ull s_G[256];             // dup-packed Gram           (2 KB)
    __shared__ ull s_m1[16];

    const float4* cf4 = (const float4*)(g_coeffT
        + ((size_t)(br * Bn + b) * Cn + c0) * 16);
    for (int i = tid; i < 512; i += 192) {
        float4 v = cf4[i];
        ull p0, p1, p2, p3;
        PK2(p0, v.x, v.x); PK2(p1, v.y, v.y); PK2(p2, v.z, v.z); PK2(p3, v.w, v.w);
        s_cf[4 * i + 0] = p0; s_cf[4 * i + 1] = p1;
        s_cf[4 * i + 2] = p2; s_cf[4 * i + 3] = p3;
    }
    for (int i = tid; i < 256; i += 192) {
        float gg = g_G[(br * Bn + b) * 256 + i];
        ull g2; PK2(g2, gg, gg);
        s_G[i] = g2;
    }
    if (tid < 128) {
        float A = lng[c0 + tid], Bc = lnb[c0 + tid];
        ull a2, b2; PK2(a2, A, A); PK2(b2, Bc, Bc);
        s_gb[tid] = make_ulonglong2(a2, b2);
    } else if (tid < 144) {
        float s = g_s1[(br * Bn + b) * 16 + tid - 128];
        ull s2; PK2(s2, s, s);
        s_m1[tid - 128] = s2;
    }
    __syncthreads();

    int p0 = chunk * 384 + tid * 2;
    const float* ub = g_UP + ((size_t)b * 3 + br) * 16 * HWn;
    ull u[16];
#pragma unroll
    for (int n = 0; n < 16; ++n) {
        float2 v = *(const float2*)(ub + (size_t)n * HWn + p0);
        PK2(u[n], v.x, v.y);
    }

    // LN stats: mean + E[x^2] via Gram quadratic form (padding rows are zero)
    ull m = 0ull, q = 0ull;
#pragma unroll
    for (int n = 0; n < 16; ++n) FMA2(m, s_m1[n], u[n], m);
#pragma unroll
    for (int n = 0; n < 16; ++n) {
        ull t = 0ull;
#pragma unroll
        for (int mm = 0; mm < 16; ++mm) FMA2(t, s_G[n * 16 + mm], u[mm], t);
        FMA2(q, t, u[n], q);
    }
    float mx, my, qx, qy;
    UPK2(mx, my, m); UPK2(qx, qy, q);
    float rx = rsqrtf(fmaxf(qx - mx * mx, 0.f) + 1e-5f);
    float ry = rsqrtf(fmaxf(qy - my * my, 0.f) + 1e-5f);
    ull r2, nm;
    PK2(r2, rx, ry);
    PK2(nm, -mx, -my);

    float* ob = out + (size_t)br * Bn * Cn * HWn + (size_t)b * Cn * HWn
              + (size_t)c0 * HWn + p0;
#pragma unroll 4
    for (int c = 0; c < 128; ++c) {
        // 4 independent accumulator chains (depth 4 each), tree combine
        ull v0 = 0ull, v1 = 0ull, v2 = 0ull, v3 = 0ull;
        const ulonglong2* w2 = (const ulonglong2*)(s_cf + c * 16);
        ulonglong2 wa = w2[0], wb = w2[1], wc = w2[2], wd = w2[3];
        FMA2(v0, wa.x, u[0],  v0); FMA2(v1, wa.y, u[1],  v1);
        FMA2(v2, wb.x, u[2],  v2); FMA2(v3, wb.y, u[3],  v3);
        FMA2(v0, wc.x, u[4],  v0); FMA2(v1, wc.y, u[5],  v1);
        FMA2(v2, wd.x, u[6],  v2); FMA2(v3, wd.y, u[7],  v3);
        wa = w2[4]; wb = w2[5]; wc = w2[6]; wd = w2[7];
        FMA2(v0, wa.x, u[8],  v0); FMA2(v1, wa.y, u[9],  v1);
        FMA2(v2, wb.x, u[10], v2); FMA2(v3, wb.y, u[11], v3);
        FMA2(v0, wc.x, u[12], v0); FMA2(v1, wc.y, u[13], v1);
        FMA2(v2, wd.x, u[14], v2); FMA2(v3, wd.y, u[15], v3);
        ull va, vb, v;
        ADD2(va, v0, v1); ADD2(vb, v2, v3); ADD2(v, va, vb);

        ulonglong2 gb = s_gb[c];
        ull rA, bias, o;
        MUL2(rA, r2, gb.x);
        FMA2(bias, nm, rA, gb.y);
        FMA2(o, v, rA, bias);
        *(ull*)(ob + (size_t)c * HWn) = o;
    }
}

// ---------------------------------------------------------------------------
extern "C" void kernel_launch(void* const* d_in, const int* in_sizes, int n_in,
                              void* d_out, int out_size) {
    const float* feat = (const float*)d_in[0];
    const float* iw1 = (const float*)d_in[1];
    const float* ib1 = (const float*)d_in[2];
    const float* iw2 = (const float*)d_in[3];
    const float* ib2 = (const float*)d_in[4];
    const float* ew1 = (const float*)d_in[5];
    const float* eb1 = (const float*)d_in[6];
    const float* ew2 = (const float*)d_in[7];
    const float* eb2 = (const float*)d_in[8];
    const float* cw1 = (const float*)d_in[9];
    const float* cb1 = (const float*)d_in[10];
    const float* cw2 = (const float*)d_in[11];
    const float* cb2 = (const float*)d_in[12];
    const float* rw1 = (const float*)d_in[13];
    const float* rb1 = (const float*)d_in[14];
    const float* rw2 = (const float*)d_in[15];
    const float* rb2 = (const float*)d_in[16];
    const float* lig = (const float*)d_in[17];
    const float* lib = (const float*)d_in[18];
    const float* leg = (const float*)d_in[19];
    const float* leb = (const float*)d_in[20];
    const float* lcg = (const float*)d_in[21];
    const float* lcb = (const float*)d_in[22];
    float* out = (float*)d_out;

    k_prep<<<145, 256>>>(rw1, rb1, rw2, rb2);
    k_reduce<<<dim3(16, Bn), 288>>>(feat);
    k_mix<<<688, 288>>>(iw1, ib1, iw2, ib2, ew1, eb1, ew2, eb2, cw1, cb1, cw2, cb2);
    k_main<<<dim3(6, Bn, 6), 192>>>(lig, lib, leg, leb, lcg, lcb, out);
}

// round 14
// speedup vs baseline: 1.0303x; 1.0303x over previous
#include <cuda_runtime.h>
#include <math.h>

#define Bn   16
#define Cn   256
#define Hn   48
#define Wn   48
#define HWn  2304
#define NG   40
#define KK   49

typedef unsigned long long ull;

// f32x2 packed-math macros (sm_103a FFMA2 path)
#define FMA2(d,a,b,c) asm("fma.rn.f32x2 %0, %1, %2, %3;" : "=l"(d) : "l"(a), "l"(b), "l"(c))
#define MUL2(d,a,b)   asm("mul.rn.f32x2 %0, %1, %2;"     : "=l"(d) : "l"(a), "l"(b))
#define ADD2(d,a,b)   asm("add.rn.f32x2 %0, %1, %2;"     : "=l"(d) : "l"(a), "l"(b))
#define PK2(d,lo,hi)  asm("mov.b64 %0, {%1, %2};"        : "=l"(d) : "f"(lo), "f"(hi))
#define UPK2(lo,hi,s) asm("mov.b64 {%0, %1}, %2;"        : "=f"(lo), "=f"(hi) : "l"(s))

// Scratch (device globals, zero-initialized at load; padding never written)
__device__ float g_z[Bn * Cn];                                  // GAP [B,C]
__device__ __align__(16) float g_fs[Bn * HWn];                  // channel sum
__device__ float g_basis[NG * KK];                              // bases
__device__ __align__(16) float g_coeffT[3 * Bn * Cn * 16];      // [br,b,c,16n] padded
__device__ float g_G[3 * Bn * 256];                             // Gram/C, n*16+m padded
__device__ float g_s1[3 * Bn * 16];                             // colmean/C padded
__device__ __align__(16) float g_UP[(size_t)Bn * 3 * 16 * HWn]; // [b,br,16n,HW] padded

// ---------------------------------------------------------------------------
// k_prep: block 0 computes the 40 basis kernels; blocks 1..144 zero g_fs
__global__ void k_prep(const float* __restrict__ rw1, const float* __restrict__ rb1,
                       const float* __restrict__ rw2, const float* __restrict__ rb2) {
    int tid = threadIdx.x;
    if (blockIdx.x > 0) {
        int i = (blockIdx.x - 1) * 256 + tid;   // 144*256 = Bn*HWn
        g_fs[i] = 0.f;
        return;
    }
    __shared__ float r[KK], th[KK];
    if (tid < KK) {
        int i = tid / 7, j = tid % 7;
        float gy = (float)i - 3.f, gx = (float)j - 3.f;
        r[tid] = sqrtf(gx * gx + gy * gy + 1e-8f);
        th[tid] = atan2f(gy, gx);
    }
    __syncthreads();

    if (tid < 24) {
        bool inv = tid < 8;
        int i = inv ? tid : (tid - 8);
        int combo = i % 9;
        int d = combo / 3, si = combo % 3;
        float sig = inv ? (4.f + 2.f * (float)si) : (1.f + (float)si);
        float psi[KK];
        float ss = 0.f;
        for (int c = 0; c < KK; ++c) {
            float u = r[c] / sig;
            float g = expf(-0.5f * u * u);
            float p = (d == 0) ? 1.f : ((d == 1) ? u : (u * u - 1.f));
            psi[c] = p * g;
            ss += psi[c] * psi[c];
        }
        float inorm = 1.f / sqrtf(ss + 1e-8f);
        int gi = inv ? tid : (8 + i);
        for (int c = 0; c < KK; ++c) g_basis[gi * KK + c] = psi[c] * inorm;
    }

    if (tid < KK) {
        float rad0 = rb2[0], rad1 = rb2[1];
        for (int h = 0; h < 32; ++h) {
            float t = tanhf(r[tid] * rw1[h] + rb1[h]);
            rad0 += t * rw2[h * 2 + 0];
            rad1 += t * rw2[h * 2 + 1];
        }
        for (int l = 0; l < 8; ++l) {
            float o = (float)(l / 2 + 1);
            float a = (l & 1) ? sinf(o * th[tid]) : cosf(o * th[tid]);
            g_basis[(24 + l) * KK + tid]     = rad0 * a;
            g_basis[(24 + 8 + l) * KK + tid] = rad1 * a;
        }
    }
}

// ---------------------------------------------------------------------------
// k_reduce: float4 loads, same algorithm/atomics as champion.
// grid (16, B), block 288.
__global__ void k_reduce(const float* __restrict__ feat) {
    int b = blockIdx.y, chunk = blockIdx.x, tid = threadIdx.x;
    int lane = tid & 31, w = tid >> 5;           // 9 warps
    __shared__ float zs[16][9];

    float4 f0 = make_float4(0.f, 0.f, 0.f, 0.f);
    float4 f1 = make_float4(0.f, 0.f, 0.f, 0.f);
    const float4* fb = (const float4*)(feat + ((size_t)b * Cn + chunk * 16) * HWn);
    for (int c = 0; c < 16; ++c) {
        const float4* fp = fb + (size_t)c * (HWn / 4);
        float4 a = fp[tid];
        float4 d = fp[tid + 288];
        f0.x += a.x; f0.y += a.y; f0.z += a.z; f0.w += a.w;
        f1.x += d.x; f1.y += d.y; f1.z += d.z; f1.w += d.w;
        float cs = a.x + a.y + a.z + a.w + d.x + d.y + d.z + d.w;
#pragma unroll
        for (int o = 16; o; o >>= 1) cs += __shfl_xor_sync(0xffffffffu, cs, o);
        if (lane == 0) zs[c][w] = cs;
    }
    __syncthreads();
    if (tid < 16) {
        float s = 0.f;
#pragma unroll
        for (int i = 0; i < 9; ++i) s += zs[tid][i];
        g_z[b * Cn + chunk * 16 + tid] = s * (1.f / (float)HWn);
    }
    float* fsb = g_fs + b * HWn;
    atomicAdd(&fsb[4 * tid + 0], f0.x);
    atomicAdd(&fsb[4 * tid + 1], f0.y);
    atomicAdd(&fsb[4 * tid + 2], f0.z);
    atomicAdd(&fsb[4 * tid + 3], f0.w);
    atomicAdd(&fsb[1152 + 4 * tid + 0], f1.x);
    atomicAdd(&fsb[1152 + 4 * tid + 1], f1.y);
    atomicAdd(&fsb[1152 + 4 * tid + 2], f1.z);
    atomicAdd(&fsb[1152 + 4 * tid + 3], f1.w);
}

// ---------------------------------------------------------------------------
// k_mix: blockIdx-split fused kernel. Blocks 0..47 run the MLP (br,b);
// blocks 48..687 run uconv (g,b). Block 288 threads. Shared smem buffer.
#define SBUF_FLOATS 4672

template <int N>
__device__ __forceinline__ void mlp_body(
    int br, int b, int tid,
    const float* __restrict__ w1, const float* __restrict__ b1,
    const float* __restrict__ w2, const float* __restrict__ b2,
    float* sbuf) {
    float* zz = sbuf;            // 256
    float* hp = sbuf + 256;      // 4*64
    float* hh = sbuf + 512;      // 64
    float* sc = sbuf + 576;      // 16*256
    const int NC = N * Cn;
    if (tid < Cn) zz[tid] = g_z[b * Cn + tid];
    __syncthreads();
    if (tid < 256) {
        int j = tid & 63, s = tid >> 6;
        float a = 0.f;
        const float* wp = w1 + (size_t)(64 * s) * 64 + j;
#pragma unroll 8
        for (int c = 0; c < 64; ++c) a += zz[64 * s + c] * wp[c * 64];
        hp[s * 64 + j] = a;
    }
    __syncthreads();
    if (tid < 64)
        hh[tid] = fmaxf(hp[tid] + hp[64 + tid] + hp[128 + tid] + hp[192 + tid] + b1[tid], 0.f);
    __syncthreads();
    if (tid < Cn) {
        int c = tid;
        float acc[N];
#pragma unroll
        for (int n = 0; n < N; ++n) acc[n] = b2[n * Cn + c];
        for (int h2 = 0; h2 < 64; ++h2) {
            float hv = hh[h2];
            const float* wp = w2 + (size_t)h2 * NC + c;
#pragma unroll
            for (int n = 0; n < N; ++n) acc[n] += hv * wp[n * Cn];
        }
#pragma unroll
        for (int n = 0; n < N; ++n) sc[n * Cn + c] = acc[n];
        // transposed, padded coeff store: [c][16] (pad stays zero)
        float4* dst = (float4*)(g_coeffT + ((size_t)(br * Bn + b) * Cn + c) * 16);
#pragma unroll
        for (int k = 0; k < N / 4; ++k)
            dst[k] = make_float4(acc[4 * k], acc[4 * k + 1], acc[4 * k + 2], acc[4 * k + 3]);
    }
    __syncthreads();
    if (tid < N * N) {
        int n = tid / N, m = tid % N;
        float a = 0.f;
#pragma unroll 4
        for (int c = 0; c < Cn; ++c) a += sc[n * Cn + c] * sc[m * Cn + c];
        g_G[(br * Bn + b) * 256 + n * 16 + m] = a * (1.f / (float)Cn);  // n*16+m padded
    } else if (tid < N * N + N) {
        int n = tid - N * N;
        float a = 0.f;
#pragma unroll 4
        for (int c = 0; c < Cn; ++c) a += sc[n * Cn + c];
        g_s1[(br * Bn + b) * 16 + n] = a * (1.f / (float)Cn);
    }
}

__global__ void __launch_bounds__(288)
k_mix(const float* __restrict__ w1i, const float* __restrict__ b1i,
      const float* __restrict__ w2i, const float* __restrict__ b2i,
      const float* __restrict__ w1e, const float* __restrict__ b1e,
      const float* __restrict__ w2e, const float* __restrict__ b2e,
      const float* __restrict__ w1c, const float* __restrict__ b1c,
      const float* __restrict__ w2c, const float* __restrict__ b2c) {
    __shared__ float sbuf[SBUF_FLOATS];
    int bx = blockIdx.x, tid = threadIdx.x;

    if (bx < 48) {
        int br = bx / 16, b = bx % 16;
        if (br == 0)      mlp_body<8>(0, b, tid, w1i, b1i, w2i, b2i, sbuf);
        else if (br == 1) mlp_body<16>(1, b, tid, w1e, b1e, w2e, b2e, sbuf);
        else              mlp_body<16>(2, b, tid, w1c, b1c, w2c, b2c, sbuf);
        return;
    }

    // ---- uconv role ----
    int gb = bx - 48;
    int g = gb % NG, b = gb / NG;
    int br = (g < 8) ? 0 : ((g < 24) ? 1 : 2);
    int nl = g - ((br == 0) ? 0 : ((br == 1) ? 8 : 24));
    float* fp = sbuf;            // 54*54 = 2916
    float* bs = sbuf + 2916;     // 49
    if (tid < KK) bs[tid] = g_basis[g * KK + tid];
    for (int i = tid; i < 54 * 54; i += 288) {
        int row = i / 54, col = i % 54;
        int y = row - 3, x = col - 3;
        fp[i] = (y >= 0 && y < Hn && x >= 0 && x < Wn) ? g_fs[b * HWn + y * Wn + x] : 0.f;
    }
    __syncthreads();

    int x = tid % 48, yg0 = tid / 48;   // yg0 in 0..5
    float* up = g_UP + (((size_t)b * 3 + br) * 16 + nl) * HWn;
#pragma unroll
    for (int it = 0; it < 2; ++it) {
        int y0 = (yg0 + 6 * it) * 4;    // 4 vertically adjacent outputs
        float a0 = 0.f, a1 = 0.f, a2 = 0.f, a3 = 0.f;
#pragma unroll
        for (int ri = 0; ri < 10; ++ri) {
            float t[7];
#pragma unroll
            for (int dx = 0; dx < 7; ++dx) t[dx] = fp[(y0 + ri) * 54 + x + dx];
#pragma unroll
            for (int o = 0; o < 4; ++o) {
                int dy = ri - o;
                if (dy >= 0 && dy < 7) {
                    float s = 0.f;
#pragma unroll
                    for (int dx = 0; dx < 7; ++dx) s += t[dx] * bs[dy * 7 + dx];
                    if (o == 0) a0 += s; else if (o == 1) a1 += s;
                    else if (o == 2) a2 += s; else a3 += s;
                }
            }
        }
        up[(y0 + 0) * Wn + x] = a0;
        up[(y0 + 1) * Wn + x] = a1;
        up[(y0 + 2) * Wn + x] = a2;
        up[(y0 + 3) * Wn + x] = a3;
    }
}

// ---------------------------------------------------------------------------
// k_main v3: channel-split. grid (6, B, 6): z = br*2 + half (128 ch each).
// 576 blocks (~4/SM), block 192, 2 px/thread, 4 independent FFMA2 chains.
__global__ void __launch_bounds__(192)
k_main(const float* __restrict__ lig, const float* __restrict__ lib,
       const float* __restrict__ leg, const float* __restrict__ leb,
       const float* __restrict__ lcg, const float* __restrict__ lcb,
       float* __restrict__ out) {
    int chunk = blockIdx.x, b = blockIdx.y;
    int br = blockIdx.z >> 1, half = blockIdx.z & 1;
    int c0 = half << 7;                  // 0 or 128
    int tid = threadIdx.x;

    const float* lng = (br == 0) ? lig : ((br == 1) ? leg : lcg);
    const float* lnb = (br == 0) ? lib : ((br == 1) ? leb : lcb);

    __shared__ ull s_cf[128 * 16];       // dup-packed coeffs [c][n]  (16 KB)
    __shared__ ulonglong2 s_gb[128];     // (gamma2, beta2)           (2 KB)
    __shared__ ull s_G[256];             // dup-packed Gram           (2 KB)
    __shared__ ull s_m1[16];

    const float4* cf4 = (const float4*)(g_coeffT
        + ((size_t)(br * Bn + b) * Cn + c0) * 16);
    for (int i = tid; i < 512; i += 192) {
        float4 v = cf4[i];
        ull p0, p1, p2, p3;
        PK2(p0, v.x, v.x); PK2(p1, v.y, v.y); PK2(p2, v.z, v.z); PK2(p3, v.w, v.w);
        s_cf[4 * i + 0] = p0; s_cf[4 * i + 1] = p1;
        s_cf[4 * i + 2] = p2; s_cf[4 * i + 3] = p3;
    }
    for (int i = tid; i < 256; i += 192) {
        float gg = g_G[(br * Bn + b) * 256 + i];
        ull g2; PK2(g2, gg, gg);
        s_G[i] = g2;
    }
    if (tid < 128) {
        float A = lng[c0 + tid], Bc = lnb[c0 + tid];
        ull a2, b2; PK2(a2, A, A); PK2(b2, Bc, Bc);
        s_gb[tid] = make_ulonglong2(a2, b2);
    } else if (tid < 144) {
        float s = g_s1[(br * Bn + b) * 16 + tid - 128];
        ull s2; PK2(s2, s, s);
        s_m1[tid - 128] = s2;
    }
    __syncthreads();

    int p0 = chunk * 384 + tid * 2;
    const float* ub = g_UP + ((size_t)b * 3 + br) * 16 * HWn;
    ull u[16];
#pragma unroll
    for (int n = 0; n < 16; ++n) {
        float2 v = *(const float2*)(ub + (size_t)n * HWn + p0);
        PK2(u[n], v.x, v.y);
    }

    // LN stats: mean + E[x^2] via Gram quadratic form (padding rows are zero)
    ull m = 0ull, q = 0ull;
#pragma unroll
    for (int n = 0; n < 16; ++n) FMA2(m, s_m1[n], u[n], m);
#pragma unroll
    for (int n = 0; n < 16; ++n) {
        ull t = 0ull;
#pragma unroll
        for (int mm = 0; mm < 16; ++mm) FMA2(t, s_G[n * 16 + mm], u[mm], t);
        FMA2(q, t, u[n], q);
    }
    float mx, my, qx, qy;
    UPK2(mx, my, m); UPK2(qx, qy, q);
    float rx = rsqrtf(fmaxf(qx - mx * mx, 0.f) + 1e-5f);
    float ry = rsqrtf(fmaxf(qy - my * my, 0.f) + 1e-5f);
    ull r2, nm;
    PK2(r2, rx, ry);
    PK2(nm, -mx, -my);

    float* ob = out + (size_t)br * Bn * Cn * HWn + (size_t)b * Cn * HWn
              + (size_t)c0 * HWn + p0;
#pragma unroll 4
    for (int c = 0; c < 128; ++c) {
        // 4 independent accumulator chains (depth 4 each), tree combine
        ull v0 = 0ull, v1 = 0ull, v2 = 0ull, v3 = 0ull;
        const ulonglong2* w2 = (const ulonglong2*)(s_cf + c * 16);
        ulonglong2 wa = w2[0], wb = w2[1], wc = w2[2], wd = w2[3];
        FMA2(v0, wa.x, u[0],  v0); FMA2(v1, wa.y, u[1],  v1);
        FMA2(v2, wb.x, u[2],  v2); FMA2(v3, wb.y, u[3],  v3);
        FMA2(v0, wc.x, u[4],  v0); FMA2(v1, wc.y, u[5],  v1);
        FMA2(v2, wd.x, u[6],  v2); FMA2(v3, wd.y, u[7],  v3);
        wa = w2[4]; wb = w2[5]; wc = w2[6]; wd = w2[7];
        FMA2(v0, wa.x, u[8],  v0); FMA2(v1, wa.y, u[9],  v1);
        FMA2(v2, wb.x, u[10], v2); FMA2(v3, wb.y, u[11], v3);
        FMA2(v0, wc.x, u[12], v0); FMA2(v1, wc.y, u[13], v1);
        FMA2(v2, wd.x, u[14], v2); FMA2(v3, wd.y, u[15], v3);
        ull va, vb, v;
        ADD2(va, v0, v1); ADD2(vb, v2, v3); ADD2(v, va, vb);

        ulonglong2 gb = s_gb[c];
        ull rA, bias, o;
        MUL2(rA, r2, gb.x);
        FMA2(bias, nm, rA, gb.y);
        FMA2(o, v, rA, bias);
        *(ull*)(ob + (size_t)c * HWn) = o;
    }
}

// ---------------------------------------------------------------------------
extern "C" void kernel_launch(void* const* d_in, const int* in_sizes, int n_in,
                              void* d_out, int out_size) {
    const float* feat = (const float*)d_in[0];
    const float* iw1 = (const float*)d_in[1];
    const float* ib1 = (const float*)d_in[2];
    const float* iw2 = (const float*)d_in[3];
    const float* ib2 = (const float*)d_in[4];
    const float* ew1 = (const float*)d_in[5];
    const float* eb1 = (const float*)d_in[6];
    const float* ew2 = (const float*)d_in[7];
    const float* eb2 = (const float*)d_in[8];
    const float* cw1 = (const float*)d_in[9];
    const float* cb1 = (const float*)d_in[10];
    const float* cw2 = (const float*)d_in[11];
    const float* cb2 = (const float*)d_in[12];
    const float* rw1 = (const float*)d_in[13];
    const float* rb1 = (const float*)d_in[14];
    const float* rw2 = (const float*)d_in[15];
    const float* rb2 = (const float*)d_in[16];
    const float* lig = (const float*)d_in[17];
    const float* lib = (const float*)d_in[18];
    const float* leg = (const float*)d_in[19];
    const float* leb = (const float*)d_in[20];
    const float* lcg = (const float*)d_in[21];
    const float* lcb = (const float*)d_in[22];
    float* out = (float*)d_out;

    k_prep<<<145, 256>>>(rw1, rb1, rw2, rb2);
    k_reduce<<<dim3(16, Bn), 288>>>(feat);
    k_mix<<<688, 288>>>(iw1, ib1, iw2, ib2, ew1, eb1, ew2, eb2, cw1, cb1, cw2, cb2);
    k_main<<<dim3(6, Bn, 6), 192>>>(lig, lib, leg, leb, lcg, lcb, out);
}

// round 15
// speedup vs baseline: 1.0539x; 1.0228x over previous
#include <cuda_runtime.h>
#include <math.h>

#define Bn   16
#define Cn   256
#define Hn   48
#define Wn   48
#define HWn  2304
#define NG   40
#define KK   49

typedef unsigned long long ull;

// f32x2 packed-math macros (sm_103a FFMA2 path)
#define FMA2(d,a,b,c) asm("fma.rn.f32x2 %0, %1, %2, %3;" : "=l"(d) : "l"(a), "l"(b), "l"(c))
#define MUL2(d,a,b)   asm("mul.rn.f32x2 %0, %1, %2;"     : "=l"(d) : "l"(a), "l"(b))
#define ADD2(d,a,b)   asm("add.rn.f32x2 %0, %1, %2;"     : "=l"(d) : "l"(a), "l"(b))
#define PK2(d,lo,hi)  asm("mov.b64 %0, {%1, %2};"        : "=l"(d) : "f"(lo), "f"(hi))
#define UPK2(lo,hi,s) asm("mov.b64 {%0, %1}, %2;"        : "=f"(lo), "=f"(hi) : "l"(s))

// Scratch (device globals, zero-initialized at load; padding never written)
__device__ float g_z[Bn * Cn];                                  // GAP [B,C]
__device__ __align__(16) float g_fs[Bn * HWn];                  // channel sum
__device__ float g_basis[NG * KK];                              // bases
__device__ __align__(16) float g_coeffT[3 * Bn * Cn * 16];      // [br,b,c,16n] padded
__device__ float g_G[3 * Bn * 256];                             // Gram/C, n*16+m padded
__device__ float g_s1[3 * Bn * 16];                             // colmean/C padded
__device__ __align__(16) float g_UP[(size_t)Bn * 3 * 16 * HWn]; // [b,br,16n,HW] padded

// ---------------------------------------------------------------------------
// k_prep: block 0 computes the 40 basis kernels; blocks 1..144 zero g_fs
__global__ void k_prep(const float* __restrict__ rw1, const float* __restrict__ rb1,
                       const float* __restrict__ rw2, const float* __restrict__ rb2) {
    int tid = threadIdx.x;
    if (blockIdx.x > 0) {
        int i = (blockIdx.x - 1) * 256 + tid;   // 144*256 = Bn*HWn
        g_fs[i] = 0.f;
        return;
    }
    __shared__ float r[KK], th[KK];
    if (tid < KK) {
        int i = tid / 7, j = tid % 7;
        float gy = (float)i - 3.f, gx = (float)j - 3.f;
        r[tid] = sqrtf(gx * gx + gy * gy + 1e-8f);
        th[tid] = atan2f(gy, gx);
    }
    __syncthreads();

    if (tid < 24) {
        bool inv = tid < 8;
        int i = inv ? tid : (tid - 8);
        int combo = i % 9;
        int d = combo / 3, si = combo % 3;
        float sig = inv ? (4.f + 2.f * (float)si) : (1.f + (float)si);
        float psi[KK];
        float ss = 0.f;
        for (int c = 0; c < KK; ++c) {
            float u = r[c] / sig;
            float g = expf(-0.5f * u * u);
            float p = (d == 0) ? 1.f : ((d == 1) ? u : (u * u - 1.f));
            psi[c] = p * g;
            ss += psi[c] * psi[c];
        }
        float inorm = 1.f / sqrtf(ss + 1e-8f);
        int gi = inv ? tid : (8 + i);
        for (int c = 0; c < KK; ++c) g_basis[gi * KK + c] = psi[c] * inorm;
    }

    if (tid < KK) {
        float rad0 = rb2[0], rad1 = rb2[1];
        for (int h = 0; h < 32; ++h) {
            float t = tanhf(r[tid] * rw1[h] + rb1[h]);
            rad0 += t * rw2[h * 2 + 0];
            rad1 += t * rw2[h * 2 + 1];
        }
        for (int l = 0; l < 8; ++l) {
            float o = (float)(l / 2 + 1);
            float a = (l & 1) ? sinf(o * th[tid]) : cosf(o * th[tid]);
            g_basis[(24 + l) * KK + tid]     = rad0 * a;
            g_basis[(24 + 8 + l) * KK + tid] = rad1 * a;
        }
    }
}

// ---------------------------------------------------------------------------
// k_reduce: float4 loads. grid (16, B), block 288.
__global__ void k_reduce(const float* __restrict__ feat) {
    int b = blockIdx.y, chunk = blockIdx.x, tid = threadIdx.x;
    int lane = tid & 31, w = tid >> 5;           // 9 warps
    __shared__ float zs[16][9];

    float4 f0 = make_float4(0.f, 0.f, 0.f, 0.f);
    float4 f1 = make_float4(0.f, 0.f, 0.f, 0.f);
    const float4* fb = (const float4*)(feat + ((size_t)b * Cn + chunk * 16) * HWn);
    for (int c = 0; c < 16; ++c) {
        const float4* fp = fb + (size_t)c * (HWn / 4);
        float4 a = fp[tid];
        float4 d = fp[tid + 288];
        f0.x += a.x; f0.y += a.y; f0.z += a.z; f0.w += a.w;
        f1.x += d.x; f1.y += d.y; f1.z += d.z; f1.w += d.w;
        float cs = a.x + a.y + a.z + a.w + d.x + d.y + d.z + d.w;
#pragma unroll
        for (int o = 16; o; o >>= 1) cs += __shfl_xor_sync(0xffffffffu, cs, o);
        if (lane == 0) zs[c][w] = cs;
    }
    __syncthreads();
    if (tid < 16) {
        float s = 0.f;
#pragma unroll
        for (int i = 0; i < 9; ++i) s += zs[tid][i];
        g_z[b * Cn + chunk * 16 + tid] = s * (1.f / (float)HWn);
    }
    float* fsb = g_fs + b * HWn;
    atomicAdd(&fsb[4 * tid + 0], f0.x);
    atomicAdd(&fsb[4 * tid + 1], f0.y);
    atomicAdd(&fsb[4 * tid + 2], f0.z);
    atomicAdd(&fsb[4 * tid + 3], f0.w);
    atomicAdd(&fsb[1152 + 4 * tid + 0], f1.x);
    atomicAdd(&fsb[1152 + 4 * tid + 1], f1.y);
    atomicAdd(&fsb[1152 + 4 * tid + 2], f1.z);
    atomicAdd(&fsb[1152 + 4 * tid + 3], f1.w);
}

// ---------------------------------------------------------------------------
// k_mix: blockIdx-split fused kernel. Blocks 0..47 run the MLP (br,b);
// blocks 48..687 run uconv (g,b). Block 288 threads. Shared smem buffer.
#define SBUF_FLOATS 4672

template <int N>
__device__ __forceinline__ void mlp_body(
    int br, int b, int tid,
    const float* __restrict__ w1, const float* __restrict__ b1,
    const float* __restrict__ w2, const float* __restrict__ b2,
    float* sbuf) {
    float* zz = sbuf;            // 256
    float* hp = sbuf + 256;      // 4*64
    float* hh = sbuf + 512;      // 64
    float* sc = sbuf + 576;      // 16*256
    const int NC = N * Cn;
    if (tid < Cn) zz[tid] = g_z[b * Cn + tid];
    __syncthreads();
    if (tid < 256) {
        int j = tid & 63, s = tid >> 6;
        float a = 0.f;
        const float* wp = w1 + (size_t)(64 * s) * 64 + j;
#pragma unroll 8
        for (int c = 0; c < 64; ++c) a += zz[64 * s + c] * wp[c * 64];
        hp[s * 64 + j] = a;
    }
    __syncthreads();
    if (tid < 64)
        hh[tid] = fmaxf(hp[tid] + hp[64 + tid] + hp[128 + tid] + hp[192 + tid] + b1[tid], 0.f);
    __syncthreads();
    if (tid < Cn) {
        int c = tid;
        float acc[N];
#pragma unroll
        for (int n = 0; n < N; ++n) acc[n] = b2[n * Cn + c];
        for (int h2 = 0; h2 < 64; ++h2) {
            float hv = hh[h2];
            const float* wp = w2 + (size_t)h2 * NC + c;
#pragma unroll
            for (int n = 0; n < N; ++n) acc[n] += hv * wp[n * Cn];
        }
#pragma unroll
        for (int n = 0; n < N; ++n) sc[n * Cn + c] = acc[n];
        // transposed, padded coeff store: [c][16] (pad stays zero)
        float4* dst = (float4*)(g_coeffT + ((size_t)(br * Bn + b) * Cn + c) * 16);
#pragma unroll
        for (int k = 0; k < N / 4; ++k)
            dst[k] = make_float4(acc[4 * k], acc[4 * k + 1], acc[4 * k + 2], acc[4 * k + 3]);
    }
    __syncthreads();
    if (tid < N * N) {
        int n = tid / N, m = tid % N;
        float a = 0.f;
#pragma unroll 4
        for (int c = 0; c < Cn; ++c) a += sc[n * Cn + c] * sc[m * Cn + c];
        g_G[(br * Bn + b) * 256 + n * 16 + m] = a * (1.f / (float)Cn);  // n*16+m padded
    } else if (tid < N * N + N) {
        int n = tid - N * N;
        float a = 0.f;
#pragma unroll 4
        for (int c = 0; c < Cn; ++c) a += sc[n * Cn + c];
        g_s1[(br * Bn + b) * 16 + n] = a * (1.f / (float)Cn);
    }
}

__global__ void __launch_bounds__(288)
k_mix(const float* __restrict__ w1i, const float* __restrict__ b1i,
      const float* __restrict__ w2i, const float* __restrict__ b2i,
      const float* __restrict__ w1e, const float* __restrict__ b1e,
      const float* __restrict__ w2e, const float* __restrict__ b2e,
      const float* __restrict__ w1c, const float* __restrict__ b1c,
      const float* __restrict__ w2c, const float* __restrict__ b2c) {
    __shared__ float sbuf[SBUF_FLOATS];
    int bx = blockIdx.x, tid = threadIdx.x;

    if (bx < 48) {
        int br = bx / 16, b = bx % 16;
        if (br == 0)      mlp_body<8>(0, b, tid, w1i, b1i, w2i, b2i, sbuf);
        else if (br == 1) mlp_body<16>(1, b, tid, w1e, b1e, w2e, b2e, sbuf);
        else              mlp_body<16>(2, b, tid, w1c, b1c, w2c, b2c, sbuf);
        return;
    }

    // ---- uconv role ----
    int gb = bx - 48;
    int g = gb % NG, b = gb / NG;
    int br = (g < 8) ? 0 : ((g < 24) ? 1 : 2);
    int nl = g - ((br == 0) ? 0 : ((br == 1) ? 8 : 24));
    float* fp = sbuf;            // 54*54 = 2916
    float* bs = sbuf + 2916;     // 49
    if (tid < KK) bs[tid] = g_basis[g * KK + tid];
    for (int i = tid; i < 54 * 54; i += 288) {
        int row = i / 54, col = i % 54;
        int y = row - 3, x = col - 3;
        fp[i] = (y >= 0 && y < Hn && x >= 0 && x < Wn) ? g_fs[b * HWn + y * Wn + x] : 0.f;
    }
    __syncthreads();

    int x = tid % 48, yg0 = tid / 48;   // yg0 in 0..5
    float* up = g_UP + (((size_t)b * 3 + br) * 16 + nl) * HWn;
#pragma unroll
    for (int it = 0; it < 2; ++it) {
        int y0 = (yg0 + 6 * it) * 4;    // 4 vertically adjacent outputs
        float a0 = 0.f, a1 = 0.f, a2 = 0.f, a3 = 0.f;
#pragma unroll
        for (int ri = 0; ri < 10; ++ri) {
            float t[7];
#pragma unroll
            for (int dx = 0; dx < 7; ++dx) t[dx] = fp[(y0 + ri) * 54 + x + dx];
#pragma unroll
            for (int o = 0; o < 4; ++o) {
                int dy = ri - o;
                if (dy >= 0 && dy < 7) {
                    float s = 0.f;
#pragma unroll
                    for (int dx = 0; dx < 7; ++dx) s += t[dx] * bs[dy * 7 + dx];
                    if (o == 0) a0 += s; else if (o == 1) a1 += s;
                    else if (o == 2) a2 += s; else a3 += s;
                }
            }
        }
        up[(y0 + 0) * Wn + x] = a0;
        up[(y0 + 1) * Wn + x] = a1;
        up[(y0 + 2) * Wn + x] = a2;
        up[(y0 + 3) * Wn + x] = a3;
    }
}

// ---------------------------------------------------------------------------
// k_main v4: 4 px/thread, STG.128, template N (8 for inv), channel-split 128.
// grid (3, B, 6): z = br*2 + half. block 192.
template <int N>
__device__ __forceinline__ void main_body(
    int br, int b, int chunk, int c0, int tid,
    const float* __restrict__ lng, const float* __restrict__ lnb,
    float* __restrict__ out, ull* s_cf, ulonglong2* s_gb, ull* s_G, ull* s_m1) {

    // fill smem: coeffs (dup-packed), gamma/beta, Gram, colmean
    const float4* cf4 = (const float4*)(g_coeffT + (size_t)(br * Bn + b) * Cn * 16);
    const int NQ = N / 4;                         // float4 quarters per channel
    for (int i = tid; i < 128 * NQ; i += 192) {
        int ci = i / NQ, k = i % NQ;
        float4 v = cf4[(c0 + ci) * 4 + k];
        ull p0, p1, p2, p3;
        PK2(p0, v.x, v.x); PK2(p1, v.y, v.y); PK2(p2, v.z, v.z); PK2(p3, v.w, v.w);
        ull* d = s_cf + ci * N + 4 * k;
        d[0] = p0; d[1] = p1; d[2] = p2; d[3] = p3;
    }
    for (int i = tid; i < N * 16; i += 192) {     // Gram rows (stride 16)
        float gg = g_G[(br * Bn + b) * 256 + i];
        ull g2; PK2(g2, gg, gg);
        s_G[i] = g2;
    }
    if (tid < 128) {
        float A = lng[c0 + tid], Bc = lnb[c0 + tid];
        ull a2, b2; PK2(a2, A, A); PK2(b2, Bc, Bc);
        s_gb[tid] = make_ulonglong2(a2, b2);
    } else if (tid < 128 + N) {
        float s = g_s1[(br * Bn + b) * 16 + tid - 128];
        ull s2; PK2(s2, s, s);
        s_m1[tid - 128] = s2;
    }
    __syncthreads();

    int p0 = chunk * 768 + tid * 4;
    const float* ub = g_UP + ((size_t)b * 3 + br) * 16 * HWn;
    ull u[N][2];
#pragma unroll
    for (int n = 0; n < N; ++n) {
        float4 v = *(const float4*)(ub + (size_t)n * HWn + p0);
        PK2(u[n][0], v.x, v.y);
        PK2(u[n][1], v.z, v.w);
    }

    // LN stats for both pixel-pairs
    ull ma = 0ull, mb = 0ull, qa = 0ull, qb = 0ull;
#pragma unroll
    for (int n = 0; n < N; ++n) {
        FMA2(ma, s_m1[n], u[n][0], ma);
        FMA2(mb, s_m1[n], u[n][1], mb);
    }
#pragma unroll
    for (int n = 0; n < N; ++n) {
        ull ta = 0ull, tb = 0ull;
#pragma unroll
        for (int mm = 0; mm < N; ++mm) {
            ull g2 = s_G[n * 16 + mm];
            FMA2(ta, g2, u[mm][0], ta);
            FMA2(tb, g2, u[mm][1], tb);
        }
        FMA2(qa, ta, u[n][0], qa);
        FMA2(qb, tb, u[n][1], qb);
    }
    float m0, m1, m2, m3, q0, q1, q2, q3;
    UPK2(m0, m1, ma); UPK2(m2, m3, mb);
    UPK2(q0, q1, qa); UPK2(q2, q3, qb);
    float r0 = rsqrtf(fmaxf(q0 - m0 * m0, 0.f) + 1e-5f);
    float r1 = rsqrtf(fmaxf(q1 - m1 * m1, 0.f) + 1e-5f);
    float r2 = rsqrtf(fmaxf(q2 - m2 * m2, 0.f) + 1e-5f);
    float r3 = rsqrtf(fmaxf(q3 - m3 * m3, 0.f) + 1e-5f);
    ull rpa, rpb, nma, nmb;
    PK2(rpa, r0, r1); PK2(rpb, r2, r3);
    PK2(nma, -m0, -m1); PK2(nmb, -m2, -m3);

    float* ob = out + (size_t)br * Bn * Cn * HWn + (size_t)b * Cn * HWn
              + (size_t)c0 * HWn + p0;
#pragma unroll 2
    for (int c = 0; c < 128; ++c) {
        // 4 independent FFMA2 chains (2 per pixel-pair), depth N/2
        ull a0 = 0ull, a1 = 0ull, b0 = 0ull, b1 = 0ull;
        const ulonglong2* w2 = (const ulonglong2*)(s_cf + c * N);
#pragma unroll
        for (int k = 0; k < N / 2; ++k) {
            ulonglong2 w = w2[k];
            FMA2(a0, w.x, u[2 * k + 0][0], a0);
            FMA2(a1, w.y, u[2 * k + 1][0], a1);
            FMA2(b0, w.x, u[2 * k + 0][1], b0);
            FMA2(b1, w.y, u[2 * k + 1][1], b1);
        }
        ull va, vb;
        ADD2(va, a0, a1); ADD2(vb, b0, b1);

        ulonglong2 gb = s_gb[c];
        ull rAa, rAb, biasa, biasb, oa, obp;
        MUL2(rAa, rpa, gb.x);
        MUL2(rAb, rpb, gb.x);
        FMA2(biasa, nma, rAa, gb.y);
        FMA2(biasb, nmb, rAb, gb.y);
        FMA2(oa, va, rAa, biasa);
        FMA2(obp, vb, rAb, biasb);
        float4 o;
        UPK2(o.x, o.y, oa);
        UPK2(o.z, o.w, obp);
        *(float4*)(ob + (size_t)c * HWn) = o;
    }
}

__global__ void __launch_bounds__(192)
k_main(const float* __restrict__ lig, const float* __restrict__ lib,
       const float* __restrict__ leg, const float* __restrict__ leb,
       const float* __restrict__ lcg, const float* __restrict__ lcb,
       float* __restrict__ out) {
    int chunk = blockIdx.x, b = blockIdx.y;
    int br = blockIdx.z >> 1, half = blockIdx.z & 1;
    int c0 = half << 7;
    int tid = threadIdx.x;

    __shared__ ull s_cf[128 * 16];       // 16 KB (N=8 uses half)
    __shared__ ulonglong2 s_gb[128];     // 2 KB
    __shared__ ull s_G[256];             // 2 KB
    __shared__ ull s_m1[16];

    if (br == 0)
        main_body<8>(0, b, chunk, c0, tid, lig, lib, out, s_cf, s_gb, s_G, s_m1);
    else if (br == 1)
        main_body<16>(1, b, chunk, c0, tid, leg, leb, out, s_cf, s_gb, s_G, s_m1);
    else
        main_body<16>(2, b, chunk, c0, tid, lcg, lcb, out, s_cf, s_gb, s_G, s_m1);
}

// ---------------------------------------------------------------------------
extern "C" void kernel_launch(void* const* d_in, const int* in_sizes, int n_in,
                              void* d_out, int out_size) {
    const float* feat = (const float*)d_in[0];
    const float* iw1 = (const float*)d_in[1];
    const float* ib1 = (const float*)d_in[2];
    const float* iw2 = (const float*)d_in[3];
    const float* ib2 = (const float*)d_in[4];
    const float* ew1 = (const float*)d_in[5];
    const float* eb1 = (const float*)d_in[6];
    const float* ew2 = (const float*)d_in[7];
    const float* eb2 = (const float*)d_in[8];
    const float* cw1 = (const float*)d_in[9];
    const float* cb1 = (const float*)d_in[10];
    const float* cw2 = (const float*)d_in[11];
    const float* cb2 = (const float*)d_in[12];
    const float* rw1 = (const float*)d_in[13];
    const float* rb1 = (const float*)d_in[14];
    const float* rw2 = (const float*)d_in[15];
    const float* rb2 = (const float*)d_in[16];
    const float* lig = (const float*)d_in[17];
    const float* lib = (const float*)d_in[18];
    const float* leg = (const float*)d_in[19];
    const float* leb = (const float*)d_in[20];
    const float* lcg = (const float*)d_in[21];
    const float* lcb = (const float*)d_in[22];
    float* out = (float*)d_out;

    k_prep<<<145, 256>>>(rw1, rb1, rw2, rb2);
    k_reduce<<<dim3(16, Bn), 288>>>(feat);
    k_mix<<<688, 288>>>(iw1, ib1, iw2, ib2, ew1, eb1, ew2, eb2, cw1, cb1, cw2, cb2);
    k_main<<<dim3(3, Bn, 6), 192>>>(lig, lib, leg, leb, lcg, lcb, out);
}